// round 15
// baseline (speedup 1.0000x reference)
#include <cuda_runtime.h>
#include <cuda_fp16.h>
#include <cstdint>

// Problem constants (fixed shapes from reference setup_inputs)
#define NN0 50000
#define NN1 10000
#define NN2 2048
#define DIN 256
#define DHID 1000
#define NCLS 5000
#define EE0 500000
#define EE1 100000
#define KP2 1024   // K of GEMM2 padded to 1024 (zero fill)

// ---------------- device scratch (static, allocation-free; zero-init at load) ----------
// Counts are zero at kernel_launch entry: load-time init on the first call,
// and scan_rsqrt_kernel re-zeroes them after consuming on every call.
__device__ int    g_cnt_out0[NN0];
__device__ int    g_cnt_in0[NN1];
__device__ int    g_cnt_out1[NN1];
__device__ int    g_cnt_in1[NN2];
__device__ float  g_rs_out0[NN0];
__device__ float  g_rs_in0[NN1];
__device__ float  g_rs_out1[NN1];
__device__ float  g_rs_in1[NN2];
__device__ int    g_off0[NN1 + 1];
__device__ int    g_cur0[NN1];
__device__ int    g_off1[NN2 + 1];
__device__ int    g_cur1[NN2];
__device__ int    g_srcs0[EE0];
__device__ int    g_srcs1[EE1];
__device__ __half g_xh[(size_t)NN0 * DIN];       // 25.6 MB  x in fp16
__device__ __half g_agg0h[(size_t)NN1 * DIN];    // 5.1 MB   layer0 aggregate (fp16)
__device__ __half g_w1t[(size_t)DHID * DIN];     // 0.5 MB   W1^T [n][k] fp16
__device__ __half g_g1[(size_t)NN2 * DIN];       // 1 MB     G = rs_in1 * sum rs_out1*agg0 (fp16)
__device__ float  g_csum[NN2];                   // rs_in1 * sum rs_out1 (bias coefficient)
__device__ __half g_agg1h[(size_t)NN2 * KP2];    // 4.2 MB   layer1 pre-GEMM2 A (fp16, k-padded;
                                                 //          pad cols [1000,1024) stay 0 forever)
__device__ __half g_w2t[(size_t)NCLS * KP2];     // 10.2 MB  W2^T [n][k] fp16 (k-padded)

// ---------------- helpers ----------------
__device__ __forceinline__ void cp_async16(void* smem_dst, const void* gsrc, bool pred) {
    uint32_t saddr = (uint32_t)__cvta_generic_to_shared(smem_dst);
    int sz = pred ? 16 : 0;
    asm volatile("cp.async.cg.shared.global [%0], [%1], 16, %2;\n"
                 :: "r"(saddr), "l"(gsrc), "r"(sz));
}
__device__ __forceinline__ void cp_commit() { asm volatile("cp.async.commit_group;\n"); }
template <int NMAX>
__device__ __forceinline__ void cp_wait() { asm volatile("cp.async.wait_group %0;\n" :: "n"(NMAX)); }

__device__ __forceinline__ void mma_f16(float* d, const uint32_t* a, const uint32_t* b) {
    asm volatile(
        "mma.sync.aligned.m16n8k16.row.col.f32.f16.f16.f32 "
        "{%0,%1,%2,%3}, {%4,%5,%6,%7}, {%8,%9}, {%0,%1,%2,%3};\n"
        : "+f"(d[0]), "+f"(d[1]), "+f"(d[2]), "+f"(d[3])
        : "r"(a[0]), "r"(a[1]), "r"(a[2]), "r"(a[3]), "r"(b[0]), "r"(b[1]));
}

// ---------------- conv kernel: convert x->fp16 | transpose W1,W2 (legacy stream) ------------
#define CB_CONV 800
#define CB_W1 256           // 32 n-tiles x 8 k-tiles
#define CB_W2 5024          // 157 n-tiles x 32 k-tiles
#define CB_TOTAL (CB_CONV + CB_W1 + CB_W2)

__device__ __forceinline__ void transpose_tile(const float* __restrict__ W, __half* __restrict__ Wt,
                                               int K, int N, int KPad, int nb, int kb, int tid) {
    __shared__ float tile[32][33];
    int tx = tid & 31, ty = tid >> 5;  // (32,8)
#pragma unroll
    for (int i = 0; i < 32; i += 8) {
        int gk = kb + ty + i, gn = nb + tx;
        float v = 0.f;
        if (gk < K && gn < N) v = W[(size_t)gk * N + gn];
        tile[ty + i][tx] = v;
    }
    __syncthreads();
#pragma unroll
    for (int i = 0; i < 32; i += 8) {
        int gn = nb + ty + i, gk = kb + tx;
        if (gn < N && gk < KPad)
            Wt[(size_t)gn * KPad + gk] = __float2half(tile[tx][ty + i]);
    }
}

__global__ void __launch_bounds__(256) conv_kernel(const float* __restrict__ x,
                                                   const float* __restrict__ W1,
                                                   const float* __restrict__ W2) {
    int bid = blockIdx.x;
    int tid = threadIdx.x;
    if (bid < CB_CONV) {
        int i = bid * 256 + tid;
        int n4 = NN0 * DIN / 4;
        int stride = CB_CONV * 256;
        for (; i < n4; i += stride) {
            float4 v = ((const float4*)x)[i];
            __half2 h0 = __floats2half2_rn(v.x, v.y);
            __half2 h1 = __floats2half2_rn(v.z, v.w);
            uint2 u;
            u.x = *(uint32_t*)&h0;
            u.y = *(uint32_t*)&h1;
            ((uint2*)g_xh)[i] = u;
        }
    } else if (bid < CB_CONV + CB_W1) {
        int b = bid - CB_CONV;
        int nb = (b & 31) * 32;
        int kb = (b >> 5) * 32;
        transpose_tile(W1, g_w1t, DIN, DHID, DIN, nb, kb, tid);
    } else {
        int b = bid - CB_CONV - CB_W1;
        int nb = (b % 157) * 32;
        int kb = (b / 157) * 32;
        transpose_tile(W2, g_w2t, DHID, NCLS, KP2, nb, kb, tid);
    }
}

// ---------------- setup chain (side stream): degree -> scan_rsqrt(+self-zero) -> scatter ----
__global__ void degree_kernel(const int* __restrict__ s0, const int* __restrict__ d0,
                              const int* __restrict__ s1, const int* __restrict__ d1,
                              int E0, int E1) {
    int i = blockIdx.x * blockDim.x + threadIdx.x;
    int stride = gridDim.x * blockDim.x;
    for (int j = i; j < E0; j += stride) {
        atomicAdd(&g_cnt_out0[s0[j]], 1);
        atomicAdd(&g_cnt_in0[d0[j]], 1);
        if (j < E1) {
            atomicAdd(&g_cnt_out1[s1[j]], 1);
            atomicAdd(&g_cnt_in1[d1[j]], 1);
        }
    }
}

// scan + rs computation + count self-zeroing (this block is the ONLY reader of cnt)
__device__ __forceinline__ void scan_rs_zero_impl(int* cnt, int* off, int* cur,
                                                  float* rs, int NB) {
    __shared__ int wsum[32];
    int t = threadIdx.x, lane = t & 31, w = t >> 5;
    int IPT = (NB + 1023) / 1024;
    int base = t * IPT;
    int loc[10];
    int s = 0;
    for (int i = 0; i < IPT; i++) {
        int b = base + i;
        int v = 0;
        if (b < NB) {
            v = cnt[b];
            rs[b] = rsqrtf((float)max(v, 1));
            cnt[b] = 0;                       // self-zero after consuming
        }
        loc[i] = s;
        s += v;
    }
    int x = s;
    for (int d = 1; d < 32; d <<= 1) {
        int y = __shfl_up_sync(0xffffffffu, x, d);
        if (lane >= d) x += y;
    }
    if (lane == 31) wsum[w] = x;
    __syncthreads();
    if (w == 0) {
        int y = wsum[lane];
        int z = y;
        for (int d = 1; d < 32; d <<= 1) {
            int u = __shfl_up_sync(0xffffffffu, z, d);
            if (lane >= d) z += u;
        }
        wsum[lane] = z - y;
    }
    __syncthreads();
    int excl = (x - s) + wsum[w];
    // recompute running offsets from loc (cnt already zeroed; use deltas)
    for (int i = 0; i < IPT; i++) {
        int b = base + i;
        if (b < NB) {
            int o = excl + loc[i];
            off[b] = o;
            cur[b] = o;
        }
    }
    if (t == 1023) off[NB] = excl + s;
}

#define RS_BLOCKS 64
__global__ void __launch_bounds__(1024) scan_rsqrt_kernel() {
    int bid = blockIdx.x;
    if (bid == 0) { scan_rs_zero_impl(g_cnt_in0, g_off0, g_cur0, g_rs_in0, NN1); return; }
    if (bid == 1) { scan_rs_zero_impl(g_cnt_in1, g_off1, g_cur1, g_rs_in1, NN2); return; }
    int i = (bid - 2) * 1024 + threadIdx.x;
    int stride = RS_BLOCKS * 1024;
    for (int j = i; j < NN0; j += stride) {
        g_rs_out0[j] = rsqrtf((float)max(g_cnt_out0[j], 1));
        g_cnt_out0[j] = 0;                    // self-zero after consuming
    }
    for (int j = i; j < NN1; j += stride) {
        g_rs_out1[j] = rsqrtf((float)max(g_cnt_out1[j], 1));
        g_cnt_out1[j] = 0;                    // self-zero after consuming
    }
}

__global__ void scatters_kernel(const int* __restrict__ s0, const int* __restrict__ d0,
                                const int* __restrict__ s1, const int* __restrict__ d1,
                                int E0, int E1) {
    if (blockIdx.x < 1024) {
        int i = blockIdx.x * blockDim.x + threadIdx.x;
        int stride = 1024 * blockDim.x;
        for (int j = i; j < E0; j += stride) {
            int d = d0[j];
            int p = atomicAdd(&g_cur0[d], 1);
            g_srcs0[p] = s0[j];
        }
    } else {
        int i = (blockIdx.x - 1024) * blockDim.x + threadIdx.x;
        int stride = 256 * blockDim.x;
        for (int j = i; j < E1; j += stride) {
            int d = d1[j];
            int p = atomicAdd(&g_cur1[d], 1);
            g_srcs1[p] = s1[j];
        }
    }
}

// ---------------- layer-0 aggregation (fp16 gather, fp32 accum, fp16 out) ----------------
__global__ void __launch_bounds__(64) aggregate0_kernel() {
    int row = blockIdx.x;
    int t = threadIdx.x;
    int beg = g_off0[row], end = g_off0[row + 1];
    const uint2* x2 = (const uint2*)g_xh;
    float4 acc = make_float4(0.f, 0.f, 0.f, 0.f);
    int e = beg;
    for (; e + 1 < end; e += 2) {
        int s0 = g_srcs0[e], s1 = g_srcs0[e + 1];
        float c0 = g_rs_out0[s0], c1 = g_rs_out0[s1];
        uint2 u0 = x2[(size_t)s0 * (DIN / 4) + t];
        uint2 u1 = x2[(size_t)s1 * (DIN / 4) + t];
        float2 a0 = __half22float2(*(__half2*)&u0.x);
        float2 a1 = __half22float2(*(__half2*)&u0.y);
        float2 b0 = __half22float2(*(__half2*)&u1.x);
        float2 b1 = __half22float2(*(__half2*)&u1.y);
        acc.x = fmaf(a0.x, c0, acc.x); acc.y = fmaf(a0.y, c0, acc.y);
        acc.z = fmaf(a1.x, c0, acc.z); acc.w = fmaf(a1.y, c0, acc.w);
        acc.x = fmaf(b0.x, c1, acc.x); acc.y = fmaf(b0.y, c1, acc.y);
        acc.z = fmaf(b1.x, c1, acc.z); acc.w = fmaf(b1.y, c1, acc.w);
    }
    if (e < end) {
        int s0 = g_srcs0[e];
        float c0 = g_rs_out0[s0];
        uint2 u0 = x2[(size_t)s0 * (DIN / 4) + t];
        float2 a0 = __half22float2(*(__half2*)&u0.x);
        float2 a1 = __half22float2(*(__half2*)&u0.y);
        acc.x = fmaf(a0.x, c0, acc.x); acc.y = fmaf(a0.y, c0, acc.y);
        acc.z = fmaf(a1.x, c0, acc.z); acc.w = fmaf(a1.y, c0, acc.w);
    }
    float sd = g_rs_in0[row];
    __half2 o0 = __floats2half2_rn(acc.x * sd, acc.y * sd);
    __half2 o1 = __floats2half2_rn(acc.z * sd, acc.w * sd);
    uint2 ou;
    ou.x = *(uint32_t*)&o0;
    ou.y = *(uint32_t*)&o1;
    ((uint2*)g_agg0h)[(size_t)row * (DIN / 4) + t] = ou;
}

// ---------------- layer-1 pre-aggregation in INPUT space (256-dim) ----------
// G[d] = rs_in1[d] * sum_{e:dst=d} rs_out1[src]*agg0[src];  csum[d] = rs_in1[d]*sum rs_out1[src]
__global__ void __launch_bounds__(64) aggregate1p_kernel() {
    int row = blockIdx.x;
    int t = threadIdx.x;
    int beg = g_off1[row], end = g_off1[row + 1];
    const uint2* a2 = (const uint2*)g_agg0h;
    float4 acc = make_float4(0.f, 0.f, 0.f, 0.f);
    float cs = 0.f;
    int e = beg;
    for (; e + 1 < end; e += 2) {
        int s0 = g_srcs1[e], s1 = g_srcs1[e + 1];
        float c0 = g_rs_out1[s0], c1 = g_rs_out1[s1];
        cs += c0 + c1;
        uint2 u0 = a2[(size_t)s0 * (DIN / 4) + t];
        uint2 u1 = a2[(size_t)s1 * (DIN / 4) + t];
        float2 a0 = __half22float2(*(__half2*)&u0.x);
        float2 a1 = __half22float2(*(__half2*)&u0.y);
        float2 b0 = __half22float2(*(__half2*)&u1.x);
        float2 b1 = __half22float2(*(__half2*)&u1.y);
        acc.x = fmaf(a0.x, c0, acc.x); acc.y = fmaf(a0.y, c0, acc.y);
        acc.z = fmaf(a1.x, c0, acc.z); acc.w = fmaf(a1.y, c0, acc.w);
        acc.x = fmaf(b0.x, c1, acc.x); acc.y = fmaf(b0.y, c1, acc.y);
        acc.z = fmaf(b1.x, c1, acc.z); acc.w = fmaf(b1.y, c1, acc.w);
    }
    if (e < end) {
        int s0 = g_srcs1[e];
        float c0 = g_rs_out1[s0];
        cs += c0;
        uint2 u0 = a2[(size_t)s0 * (DIN / 4) + t];
        float2 a0 = __half22float2(*(__half2*)&u0.x);
        float2 a1 = __half22float2(*(__half2*)&u0.y);
        acc.x = fmaf(a0.x, c0, acc.x); acc.y = fmaf(a0.y, c0, acc.y);
        acc.z = fmaf(a1.x, c0, acc.z); acc.w = fmaf(a1.y, c0, acc.w);
    }
    float sd = g_rs_in1[row];
    __half2 o0 = __floats2half2_rn(acc.x * sd, acc.y * sd);
    __half2 o1 = __floats2half2_rn(acc.z * sd, acc.w * sd);
    uint2 ou;
    ou.x = *(uint32_t*)&o0;
    ou.y = *(uint32_t*)&o1;
    ((uint2*)g_g1)[(size_t)row * (DIN / 4) + t] = ou;
    if (t == 0) g_csum[row] = cs * sd;
}

// ---------------- fp16 GEMMs: 128x128 tile, 256 thr, 2-stage cp.async + ldmatrix ----------
// LAYER==1 (fused): A=g_g1 [2048,256], B=g_w1t [1000,256],
//                   epi: acc + csum[m]*b1[n] -> g_agg1h (fp16, row stride KP2)
// LAYER==2:         A=g_agg1h [2048,1024], B=g_w2t [5000,1024],
//                   epi: sigmoid(acc + b2[n]) -> d_out (fp32)
#define BKP 40  // 32 + 8-half pad -> 80B row stride, conflict-free ldmatrix

__device__ __forceinline__ void stage_tile(__half (*S)[BKP], const __half* __restrict__ src,
                                           int rowbase, int rowlim, int k0, int kstride, int tid) {
    int r = tid >> 1;
    int c = (tid & 1) * 16;
    bool p = (rowbase + r) < rowlim;
    size_t grow = p ? (size_t)(rowbase + r) : 0;
    const __half* g = src + grow * kstride + k0 + c;
    cp_async16(&S[r][c], g, p);
    cp_async16(&S[r][c + 8], g + 8, p);
}

template <int LAYER>
__global__ void __launch_bounds__(256) mma_gemm_kernel(const float* __restrict__ bias,
                                                       float* __restrict__ Cout) {
    constexpr int M = NN2;                            // 2048 for both layers
    constexpr int N = (LAYER == 1) ? DHID : NCLS;
    constexpr int K = (LAYER == 1) ? DIN : KP2;
    constexpr int NI = K / 32;

    const __half* __restrict__ Ah = (LAYER == 1) ? g_g1 : g_agg1h;
    const __half* __restrict__ Bh = (LAYER == 1) ? g_w1t : g_w2t;

    __shared__ __align__(16) __half As[2][128][BKP];
    __shared__ __align__(16) __half Bs[2][128][BKP];

    int tid = threadIdx.x;
    int lane = tid & 31;
    int wid = tid >> 5;
    int wm = (wid >> 2) * 64;
    int wn = (wid & 3) * 32;
    int m0 = blockIdx.y * 128, n0 = blockIdx.x * 128;

    float acc[4][4][4];
#pragma unroll
    for (int mi = 0; mi < 4; mi++)
#pragma unroll
        for (int nj = 0; nj < 4; nj++)
#pragma unroll
            for (int q = 0; q < 4; q++) acc[mi][nj][q] = 0.f;

    stage_tile(As[0], Ah, m0, M, 0, K, tid);
    stage_tile(Bs[0], Bh, n0, N, 0, K, tid);
    cp_commit();
    stage_tile(As[1], Ah, m0, M, 32, K, tid);
    stage_tile(Bs[1], Bh, n0, N, 32, K, tid);
    cp_commit();

    // ldmatrix lane address components (verified against m16n8k16 fragment spec)
    int a_row_off = wm + (lane & 7) + ((lane >> 3) & 1) * 8;  // + mi*16
    int a_col_off = (lane >> 4) * 8;                           // + kb
    int b_row_off = wn + (lane & 7) + (lane >> 4) * 8;         // + p*16
    int b_col_off = ((lane >> 3) & 1) * 8;                     // + kb

    for (int i = 0; i < NI; i++) {
        cp_wait<1>();
        __syncthreads();
        const __half (*Ab)[BKP] = As[i & 1];
        const __half (*Bb)[BKP] = Bs[i & 1];
#pragma unroll
        for (int ks = 0; ks < 2; ks++) {
            int kb = ks * 16;
            uint32_t af[4][4];
            uint32_t bf[4][2];
            uint32_t abase = (uint32_t)__cvta_generic_to_shared(&Ab[a_row_off][kb + a_col_off]);
#pragma unroll
            for (int mi = 0; mi < 4; mi++) {
                asm volatile("ldmatrix.sync.aligned.m8n8.x4.shared.b16 {%0,%1,%2,%3}, [%4];"
                             : "=r"(af[mi][0]), "=r"(af[mi][1]), "=r"(af[mi][2]), "=r"(af[mi][3])
                             : "r"(abase + (uint32_t)(mi * 16 * BKP * 2)));
            }
            uint32_t bbase = (uint32_t)__cvta_generic_to_shared(&Bb[b_row_off][kb + b_col_off]);
#pragma unroll
            for (int p = 0; p < 2; p++) {
                asm volatile("ldmatrix.sync.aligned.m8n8.x4.shared.b16 {%0,%1,%2,%3}, [%4];"
                             : "=r"(bf[2 * p][0]), "=r"(bf[2 * p][1]),
                               "=r"(bf[2 * p + 1][0]), "=r"(bf[2 * p + 1][1])
                             : "r"(bbase + (uint32_t)(p * 16 * BKP * 2)));
            }
#pragma unroll
            for (int mi = 0; mi < 4; mi++)
#pragma unroll
                for (int nj = 0; nj < 4; nj++)
                    mma_f16(acc[mi][nj], af[mi], bf[nj]);
        }
        __syncthreads();
        if (i + 2 < NI) {
            stage_tile(As[i & 1], Ah, m0, M, (i + 2) * 32, K, tid);
            stage_tile(Bs[i & 1], Bh, n0, N, (i + 2) * 32, K, tid);
        }
        cp_commit();
    }

    int er = lane >> 2;
    int ec = (lane & 3) * 2;
#pragma unroll
    for (int mi = 0; mi < 4; mi++) {
#pragma unroll
        for (int half_ = 0; half_ < 2; half_++) {
            int gm = m0 + wm + mi * 16 + er + half_ * 8;
            if (gm >= M) continue;
            float cw = (LAYER == 1) ? g_csum[gm] : 1.f;
#pragma unroll
            for (int nj = 0; nj < 4; nj++) {
                int gn = n0 + wn + nj * 8 + ec;
                if (gn >= N) continue;
                if (LAYER == 1) {
                    float v0 = acc[mi][nj][half_ * 2 + 0] + cw * bias[gn];
                    float v1 = acc[mi][nj][half_ * 2 + 1] + cw * bias[gn + 1];
                    __half2 h = __floats2half2_rn(v0, v1);
                    *(uint32_t*)&g_agg1h[(size_t)gm * KP2 + gn] = *(uint32_t*)&h;
                } else {
                    float v0 = acc[mi][nj][half_ * 2 + 0] + bias[gn];
                    float v1 = acc[mi][nj][half_ * 2 + 1] + bias[gn + 1];
                    v0 = 1.f / (1.f + __expf(-v0));
                    v1 = 1.f / (1.f + __expf(-v1));
                    *(float2*)&Cout[(size_t)gm * N + gn] = make_float2(v0, v1);
                }
            }
        }
    }
}

// ---------------- launch ----------------
extern "C" void kernel_launch(void* const* d_in, const int* in_sizes, int n_in,
                              void* d_out, int out_size) {
    const float* x  = (const float*)d_in[0];
    const float* W1 = (const float*)d_in[1];
    const float* b1 = (const float*)d_in[2];
    const float* W2 = (const float*)d_in[3];
    const float* b2 = (const float*)d_in[4];
    const int* e0_src = (const int*)d_in[5];
    const int* e0_dst = (const int*)d_in[6];
    const int* e1_src = (const int*)d_in[7];
    const int* e1_dst = (const int*)d_in[8];
    float* out = (float*)d_out;

    int E0 = in_sizes[5];
    int E1 = in_sizes[7];

    // one-time side stream + events (created on the uncaptured correctness call)
    static cudaStream_t s1 = nullptr;
    static cudaEvent_t ev_fork = nullptr, ev_join = nullptr;
    if (s1 == nullptr) {
        cudaStreamCreateWithFlags(&s1, cudaStreamNonBlocking);
        cudaEventCreateWithFlags(&ev_fork, cudaEventDisableTiming);
        cudaEventCreateWithFlags(&ev_join, cudaEventDisableTiming);
    }

    // fork: side stream runs the graph-setup chain (3 kernels; counts pre-zeroed)
    cudaEventRecord(ev_fork, 0);
    cudaStreamWaitEvent(s1, ev_fork, 0);

    degree_kernel<<<1024, 256, 0, s1>>>(e0_src, e0_dst, e1_src, e1_dst, E0, E1);
    scan_rsqrt_kernel<<<RS_BLOCKS + 2, 1024, 0, s1>>>();
    scatters_kernel<<<1280, 256, 0, s1>>>(e0_src, e0_dst, e1_src, e1_dst, E0, E1);
    cudaEventRecord(ev_join, s1);

    // legacy stream: convert + transposes in parallel
    conv_kernel<<<CB_TOTAL, 256>>>(x, W1, W2);

    // join
    cudaStreamWaitEvent(0, ev_join, 0);

    aggregate0_kernel<<<NN1, 64>>>();

    aggregate1p_kernel<<<NN2, 64>>>();

    {
        dim3 grid((DHID + 127) / 128, NN2 / 128);   // 8 x 16
        mma_gemm_kernel<1><<<grid, 256>>>(b1, nullptr);
    }

    {
        dim3 grid((NCLS + 127) / 128, NN2 / 128);   // 40 x 16
        mma_gemm_kernel<2><<<grid, 256>>>(b2, out);
    }
}

// round 16
// speedup vs baseline: 1.0046x; 1.0046x over previous
#include <cuda_runtime.h>
#include <cuda_fp16.h>
#include <cstdint>

// Problem constants (fixed shapes from reference setup_inputs)
#define NN0 50000
#define NN1 10000
#define NN2 2048
#define DIN 256
#define DHID 1000
#define NCLS 5000
#define EE0 500000
#define EE1 100000
#define KP2 1024   // K of GEMM2 padded to 1024 (zero fill)

// ---------------- device scratch (static, allocation-free) ----------------
__device__ int    g_cnt_out0[NN0];
__device__ int    g_cnt_in0[NN1];
__device__ int    g_cnt_out1[NN1];
__device__ int    g_cnt_in1[NN2];
__device__ float  g_rs_out0[NN0];
__device__ float  g_rs_in0[NN1];
__device__ float  g_rs_out1[NN1];
__device__ float  g_rs_in1[NN2];
__device__ int    g_off0[NN1 + 1];
__device__ int    g_cur0[NN1];
__device__ int    g_off1[NN2 + 1];
__device__ int    g_cur1[NN2];
__device__ int    g_srcs0[EE0];
__device__ int    g_srcs1[EE1];
__device__ __half g_xh[(size_t)NN0 * DIN];       // 25.6 MB  x in fp16
__device__ __half g_agg0h[(size_t)NN1 * DIN];    // 5.1 MB   layer0 aggregate (fp16)
__device__ __half g_w1t[(size_t)DHID * DIN];     // 0.5 MB   W1^T [n][k] fp16
__device__ __half g_g1[(size_t)NN2 * DIN];       // 1 MB     G = rs_in1 * sum rs_out1*agg0 (fp16)
__device__ float  g_csum[NN2];                   // rs_in1 * sum rs_out1 (bias coefficient)
__device__ __half g_agg1h[(size_t)NN2 * KP2];    // 4.2 MB   layer1 pre-GEMM2 A (fp16, k-padded;
                                                 //          pad cols [1000,1024) stay 0 forever)
__device__ __half g_w2t[(size_t)NCLS * KP2];     // 10.2 MB  W2^T [n][k] fp16 (k-padded)

// ---------------- helpers ----------------
__device__ __forceinline__ void cp_async16(void* smem_dst, const void* gsrc, bool pred) {
    uint32_t saddr = (uint32_t)__cvta_generic_to_shared(smem_dst);
    int sz = pred ? 16 : 0;
    asm volatile("cp.async.cg.shared.global [%0], [%1], 16, %2;\n"
                 :: "r"(saddr), "l"(gsrc), "r"(sz));
}
__device__ __forceinline__ void cp_commit() { asm volatile("cp.async.commit_group;\n"); }
template <int NMAX>
__device__ __forceinline__ void cp_wait() { asm volatile("cp.async.wait_group %0;\n" :: "n"(NMAX)); }

__device__ __forceinline__ void mma_f16(float* d, const uint32_t* a, const uint32_t* b) {
    asm volatile(
        "mma.sync.aligned.m16n8k16.row.col.f32.f16.f16.f32 "
        "{%0,%1,%2,%3}, {%4,%5,%6,%7}, {%8,%9}, {%0,%1,%2,%3};\n"
        : "+f"(d[0]), "+f"(d[1]), "+f"(d[2]), "+f"(d[3])
        : "r"(a[0]), "r"(a[1]), "r"(a[2]), "r"(a[3]), "r"(b[0]), "r"(b[1]));
}

// ---------------- conv kernel: convert x->fp16 | transpose W1,W2 (legacy stream) ------------
#define CB_CONV 800
#define CB_W1 256           // 32 n-tiles x 8 k-tiles
#define CB_W2 5024          // 157 n-tiles x 32 k-tiles
#define CB_TOTAL (CB_CONV + CB_W1 + CB_W2)

__device__ __forceinline__ void transpose_tile(const float* __restrict__ W, __half* __restrict__ Wt,
                                               int K, int N, int KPad, int nb, int kb, int tid) {
    __shared__ float tile[32][33];
    int tx = tid & 31, ty = tid >> 5;  // (32,8)
#pragma unroll
    for (int i = 0; i < 32; i += 8) {
        int gk = kb + ty + i, gn = nb + tx;
        float v = 0.f;
        if (gk < K && gn < N) v = W[(size_t)gk * N + gn];
        tile[ty + i][tx] = v;
    }
    __syncthreads();
#pragma unroll
    for (int i = 0; i < 32; i += 8) {
        int gn = nb + ty + i, gk = kb + tx;
        if (gn < N && gk < KPad)
            Wt[(size_t)gn * KPad + gk] = __float2half(tile[tx][ty + i]);
    }
}

__global__ void __launch_bounds__(256) conv_kernel(const float* __restrict__ x,
                                                   const float* __restrict__ W1,
                                                   const float* __restrict__ W2) {
    int bid = blockIdx.x;
    int tid = threadIdx.x;
    if (bid < CB_CONV) {
        int i = bid * 256 + tid;
        int n4 = NN0 * DIN / 4;
        int stride = CB_CONV * 256;
        for (; i < n4; i += stride) {
            float4 v = ((const float4*)x)[i];
            __half2 h0 = __floats2half2_rn(v.x, v.y);
            __half2 h1 = __floats2half2_rn(v.z, v.w);
            uint2 u;
            u.x = *(uint32_t*)&h0;
            u.y = *(uint32_t*)&h1;
            ((uint2*)g_xh)[i] = u;
        }
    } else if (bid < CB_CONV + CB_W1) {
        int b = bid - CB_CONV;
        int nb = (b & 31) * 32;
        int kb = (b >> 5) * 32;
        transpose_tile(W1, g_w1t, DIN, DHID, DIN, nb, kb, tid);
    } else {
        int b = bid - CB_CONV - CB_W1;
        int nb = (b % 157) * 32;
        int kb = (b / 157) * 32;
        transpose_tile(W2, g_w2t, DHID, NCLS, KP2, nb, kb, tid);
    }
}

// ---------------- setup chain (side stream) ----------------
__global__ void zero_counts_kernel() {
    int i = blockIdx.x * blockDim.x + threadIdx.x;
    int stride = gridDim.x * blockDim.x;
    for (int j = i; j < NN0; j += stride) g_cnt_out0[j] = 0;
    for (int j = i; j < NN1; j += stride) { g_cnt_in0[j] = 0; g_cnt_out1[j] = 0; }
    for (int j = i; j < NN2; j += stride) g_cnt_in1[j] = 0;
}

__global__ void degree_kernel(const int* __restrict__ s0, const int* __restrict__ d0,
                              const int* __restrict__ s1, const int* __restrict__ d1,
                              int E0, int E1) {
    int i = blockIdx.x * blockDim.x + threadIdx.x;
    int stride = gridDim.x * blockDim.x;
    for (int j = i; j < E0; j += stride) {
        atomicAdd(&g_cnt_out0[s0[j]], 1);
        atomicAdd(&g_cnt_in0[d0[j]], 1);
        if (j < E1) {
            atomicAdd(&g_cnt_out1[s1[j]], 1);
            atomicAdd(&g_cnt_in1[d1[j]], 1);
        }
    }
}

__device__ __forceinline__ void scan_impl(const int* cnt, int* off, int* cur, int NB) {
    __shared__ int wsum[32];
    int t = threadIdx.x, lane = t & 31, w = t >> 5;
    int IPT = (NB + 1023) / 1024;
    int base = t * IPT;
    int loc[10];
    int s = 0;
    for (int i = 0; i < IPT; i++) {
        int b = base + i;
        int v = (b < NB) ? cnt[b] : 0;
        loc[i] = s;
        s += v;
    }
    int x = s;
    for (int d = 1; d < 32; d <<= 1) {
        int y = __shfl_up_sync(0xffffffffu, x, d);
        if (lane >= d) x += y;
    }
    if (lane == 31) wsum[w] = x;
    __syncthreads();
    if (w == 0) {
        int y = wsum[lane];
        int z = y;
        for (int d = 1; d < 32; d <<= 1) {
            int u = __shfl_up_sync(0xffffffffu, z, d);
            if (lane >= d) z += u;
        }
        wsum[lane] = z - y;
    }
    __syncthreads();
    int excl = (x - s) + wsum[w];
    for (int i = 0; i < IPT; i++) {
        int b = base + i;
        if (b < NB) {
            int o = excl + loc[i];
            off[b] = o;
            cur[b] = o;
        }
    }
    if (t == 1023) off[NB] = excl + s;
}

#define RS_BLOCKS 64
__global__ void __launch_bounds__(1024) rsqrt_scans_kernel() {
    int bid = blockIdx.x;
    if (bid == 0) { scan_impl(g_cnt_in0, g_off0, g_cur0, NN1); return; }
    if (bid == 1) { scan_impl(g_cnt_in1, g_off1, g_cur1, NN2); return; }
    int i = (bid - 2) * 1024 + threadIdx.x;
    int stride = RS_BLOCKS * 1024;
    for (int j = i; j < NN0; j += stride)
        g_rs_out0[j] = rsqrtf((float)max(g_cnt_out0[j], 1));
    for (int j = i; j < NN1; j += stride) {
        g_rs_in0[j]  = rsqrtf((float)max(g_cnt_in0[j], 1));
        g_rs_out1[j] = rsqrtf((float)max(g_cnt_out1[j], 1));
    }
    for (int j = i; j < NN2; j += stride)
        g_rs_in1[j]  = rsqrtf((float)max(g_cnt_in1[j], 1));
}

__global__ void scatters_kernel(const int* __restrict__ s0, const int* __restrict__ d0,
                                const int* __restrict__ s1, const int* __restrict__ d1,
                                int E0, int E1) {
    if (blockIdx.x < 1024) {
        int i = blockIdx.x * blockDim.x + threadIdx.x;
        int stride = 1024 * blockDim.x;
        for (int j = i; j < E0; j += stride) {
            int d = d0[j];
            int p = atomicAdd(&g_cur0[d], 1);
            g_srcs0[p] = s0[j];
        }
    } else {
        int i = (blockIdx.x - 1024) * blockDim.x + threadIdx.x;
        int stride = 256 * blockDim.x;
        for (int j = i; j < E1; j += stride) {
            int d = d1[j];
            int p = atomicAdd(&g_cur1[d], 1);
            g_srcs1[p] = s1[j];
        }
    }
}

// ---------------- layer-0 aggregation (fp16 gather, fp32 accum, fp16 out) ----------------
__global__ void __launch_bounds__(64) aggregate0_kernel() {
    int row = blockIdx.x;
    int t = threadIdx.x;
    int beg = g_off0[row], end = g_off0[row + 1];
    const uint2* x2 = (const uint2*)g_xh;
    float4 acc = make_float4(0.f, 0.f, 0.f, 0.f);
    int e = beg;
    for (; e + 1 < end; e += 2) {
        int s0 = g_srcs0[e], s1 = g_srcs0[e + 1];
        float c0 = g_rs_out0[s0], c1 = g_rs_out0[s1];
        uint2 u0 = x2[(size_t)s0 * (DIN / 4) + t];
        uint2 u1 = x2[(size_t)s1 * (DIN / 4) + t];
        float2 a0 = __half22float2(*(__half2*)&u0.x);
        float2 a1 = __half22float2(*(__half2*)&u0.y);
        float2 b0 = __half22float2(*(__half2*)&u1.x);
        float2 b1 = __half22float2(*(__half2*)&u1.y);
        acc.x = fmaf(a0.x, c0, acc.x); acc.y = fmaf(a0.y, c0, acc.y);
        acc.z = fmaf(a1.x, c0, acc.z); acc.w = fmaf(a1.y, c0, acc.w);
        acc.x = fmaf(b0.x, c1, acc.x); acc.y = fmaf(b0.y, c1, acc.y);
        acc.z = fmaf(b1.x, c1, acc.z); acc.w = fmaf(b1.y, c1, acc.w);
    }
    if (e < end) {
        int s0 = g_srcs0[e];
        float c0 = g_rs_out0[s0];
        uint2 u0 = x2[(size_t)s0 * (DIN / 4) + t];
        float2 a0 = __half22float2(*(__half2*)&u0.x);
        float2 a1 = __half22float2(*(__half2*)&u0.y);
        acc.x = fmaf(a0.x, c0, acc.x); acc.y = fmaf(a0.y, c0, acc.y);
        acc.z = fmaf(a1.x, c0, acc.z); acc.w = fmaf(a1.y, c0, acc.w);
    }
    float sd = g_rs_in0[row];
    __half2 o0 = __floats2half2_rn(acc.x * sd, acc.y * sd);
    __half2 o1 = __floats2half2_rn(acc.z * sd, acc.w * sd);
    uint2 ou;
    ou.x = *(uint32_t*)&o0;
    ou.y = *(uint32_t*)&o1;
    ((uint2*)g_agg0h)[(size_t)row * (DIN / 4) + t] = ou;
}

// ---------------- layer-1 pre-aggregation in INPUT space (256-dim) ----------
__global__ void __launch_bounds__(64) aggregate1p_kernel() {
    int row = blockIdx.x;
    int t = threadIdx.x;
    int beg = g_off1[row], end = g_off1[row + 1];
    const uint2* a2 = (const uint2*)g_agg0h;
    float4 acc = make_float4(0.f, 0.f, 0.f, 0.f);
    float cs = 0.f;
    int e = beg;
    for (; e + 1 < end; e += 2) {
        int s0 = g_srcs1[e], s1 = g_srcs1[e + 1];
        float c0 = g_rs_out1[s0], c1 = g_rs_out1[s1];
        cs += c0 + c1;
        uint2 u0 = a2[(size_t)s0 * (DIN / 4) + t];
        uint2 u1 = a2[(size_t)s1 * (DIN / 4) + t];
        float2 a0 = __half22float2(*(__half2*)&u0.x);
        float2 a1 = __half22float2(*(__half2*)&u0.y);
        float2 b0 = __half22float2(*(__half2*)&u1.x);
        float2 b1 = __half22float2(*(__half2*)&u1.y);
        acc.x = fmaf(a0.x, c0, acc.x); acc.y = fmaf(a0.y, c0, acc.y);
        acc.z = fmaf(a1.x, c0, acc.z); acc.w = fmaf(a1.y, c0, acc.w);
        acc.x = fmaf(b0.x, c1, acc.x); acc.y = fmaf(b0.y, c1, acc.y);
        acc.z = fmaf(b1.x, c1, acc.z); acc.w = fmaf(b1.y, c1, acc.w);
    }
    if (e < end) {
        int s0 = g_srcs1[e];
        float c0 = g_rs_out1[s0];
        cs += c0;
        uint2 u0 = a2[(size_t)s0 * (DIN / 4) + t];
        float2 a0 = __half22float2(*(__half2*)&u0.x);
        float2 a1 = __half22float2(*(__half2*)&u0.y);
        acc.x = fmaf(a0.x, c0, acc.x); acc.y = fmaf(a0.y, c0, acc.y);
        acc.z = fmaf(a1.x, c0, acc.z); acc.w = fmaf(a1.y, c0, acc.w);
    }
    float sd = g_rs_in1[row];
    __half2 o0 = __floats2half2_rn(acc.x * sd, acc.y * sd);
    __half2 o1 = __floats2half2_rn(acc.z * sd, acc.w * sd);
    uint2 ou;
    ou.x = *(uint32_t*)&o0;
    ou.y = *(uint32_t*)&o1;
    ((uint2*)g_g1)[(size_t)row * (DIN / 4) + t] = ou;
    if (t == 0) g_csum[row] = cs * sd;
}

// ---------------- GEMM1 (fused bias): 128x128 tile, 256 thr, 2-stage + ldmatrix ----------
// A=g_g1 [2048,256], B=g_w1t [1000,256], epi: acc + csum[m]*b1[n] -> g_agg1h (KP2 stride)
#define BKP 40  // 32 + 8-half pad -> 80B row stride, conflict-free ldmatrix

__device__ __forceinline__ void stage_tile(__half (*S)[BKP], const __half* __restrict__ src,
                                           int rowbase, int rowlim, int k0, int kstride, int tid) {
    int r = tid >> 1;
    int c = (tid & 1) * 16;
    bool p = (rowbase + r) < rowlim;
    size_t grow = p ? (size_t)(rowbase + r) : 0;
    const __half* g = src + grow * kstride + k0 + c;
    cp_async16(&S[r][c], g, p);
    cp_async16(&S[r][c + 8], g + 8, p);
}

__global__ void __launch_bounds__(256) mma_gemm1_kernel(const float* __restrict__ bias) {
    constexpr int M = NN2, N = DHID, K = DIN;
    constexpr int NI = K / 32;

    __shared__ __align__(16) __half As[2][128][BKP];
    __shared__ __align__(16) __half Bs[2][128][BKP];

    int tid = threadIdx.x;
    int lane = tid & 31;
    int wid = tid >> 5;
    int wm = (wid >> 2) * 64;
    int wn = (wid & 3) * 32;
    int m0 = blockIdx.y * 128, n0 = blockIdx.x * 128;

    float acc[4][4][4];
#pragma unroll
    for (int mi = 0; mi < 4; mi++)
#pragma unroll
        for (int nj = 0; nj < 4; nj++)
#pragma unroll
            for (int q = 0; q < 4; q++) acc[mi][nj][q] = 0.f;

    stage_tile(As[0], g_g1, m0, M, 0, K, tid);
    stage_tile(Bs[0], g_w1t, n0, N, 0, K, tid);
    cp_commit();
    stage_tile(As[1], g_g1, m0, M, 32, K, tid);
    stage_tile(Bs[1], g_w1t, n0, N, 32, K, tid);
    cp_commit();

    int a_row_off = wm + (lane & 7) + ((lane >> 3) & 1) * 8;
    int a_col_off = (lane >> 4) * 8;
    int b_row_off = wn + (lane & 7) + (lane >> 4) * 8;
    int b_col_off = ((lane >> 3) & 1) * 8;

    for (int i = 0; i < NI; i++) {
        cp_wait<1>();
        __syncthreads();
        const __half (*Ab)[BKP] = As[i & 1];
        const __half (*Bb)[BKP] = Bs[i & 1];
#pragma unroll
        for (int ks = 0; ks < 2; ks++) {
            int kb = ks * 16;
            uint32_t af[4][4];
            uint32_t bf[4][2];
            uint32_t abase = (uint32_t)__cvta_generic_to_shared(&Ab[a_row_off][kb + a_col_off]);
#pragma unroll
            for (int mi = 0; mi < 4; mi++) {
                asm volatile("ldmatrix.sync.aligned.m8n8.x4.shared.b16 {%0,%1,%2,%3}, [%4];"
                             : "=r"(af[mi][0]), "=r"(af[mi][1]), "=r"(af[mi][2]), "=r"(af[mi][3])
                             : "r"(abase + (uint32_t)(mi * 16 * BKP * 2)));
            }
            uint32_t bbase = (uint32_t)__cvta_generic_to_shared(&Bb[b_row_off][kb + b_col_off]);
#pragma unroll
            for (int p = 0; p < 2; p++) {
                asm volatile("ldmatrix.sync.aligned.m8n8.x4.shared.b16 {%0,%1,%2,%3}, [%4];"
                             : "=r"(bf[2 * p][0]), "=r"(bf[2 * p][1]),
                               "=r"(bf[2 * p + 1][0]), "=r"(bf[2 * p + 1][1])
                             : "r"(bbase + (uint32_t)(p * 16 * BKP * 2)));
            }
#pragma unroll
            for (int mi = 0; mi < 4; mi++)
#pragma unroll
                for (int nj = 0; nj < 4; nj++)
                    mma_f16(acc[mi][nj], af[mi], bf[nj]);
        }
        __syncthreads();
        if (i + 2 < NI) {
            stage_tile(As[i & 1], g_g1, m0, M, (i + 2) * 32, K, tid);
            stage_tile(Bs[i & 1], g_w1t, n0, N, (i + 2) * 32, K, tid);
        }
        cp_commit();
    }

    int er = lane >> 2;
    int ec = (lane & 3) * 2;
#pragma unroll
    for (int mi = 0; mi < 4; mi++) {
#pragma unroll
        for (int half_ = 0; half_ < 2; half_++) {
            int gm = m0 + wm + mi * 16 + er + half_ * 8;
            if (gm >= M) continue;
            float cw = g_csum[gm];
#pragma unroll
            for (int nj = 0; nj < 4; nj++) {
                int gn = n0 + wn + nj * 8 + ec;
                if (gn >= N) continue;
                float v0 = acc[mi][nj][half_ * 2 + 0] + cw * bias[gn];
                float v1 = acc[mi][nj][half_ * 2 + 1] + cw * bias[gn + 1];
                __half2 h = __floats2half2_rn(v0, v1);
                *(uint32_t*)&g_agg1h[(size_t)gm * KP2 + gn] = *(uint32_t*)&h;
            }
        }
    }
}

// ---------------- GEMM2: 128x256 tile, 512 thr, 2-stage + ldmatrix, dynamic smem ----------
// A=g_agg1h [2048,1024], B=g_w2t [5000,1024], epi: sigmoid(+b2) -> d_out (fp32)
#define G2_SMEM ((2 * 128 * BKP + 2 * 256 * BKP) * 2)   // 61440 bytes

__global__ void __launch_bounds__(512) mma_gemm2_kernel(const float* __restrict__ bias,
                                                        float* __restrict__ Cout) {
    constexpr int M = NN2, N = NCLS, K = KP2;
    constexpr int NI = K / 32;

    extern __shared__ __align__(16) __half sm[];
    __half (*As)[128][BKP] = (__half (*)[128][BKP])sm;
    __half (*Bs)[256][BKP] = (__half (*)[256][BKP])(sm + 2 * 128 * BKP);

    int tid = threadIdx.x;
    int lane = tid & 31;
    int wid = tid >> 5;              // 0..15
    int wm = (wid >> 3) * 64;        // 0,64
    int wn = (wid & 7) * 32;         // 0..224
    int m0 = blockIdx.y * 128, n0 = blockIdx.x * 256;

    float acc[4][4][4];
#pragma unroll
    for (int mi = 0; mi < 4; mi++)
#pragma unroll
        for (int nj = 0; nj < 4; nj++)
#pragma unroll
            for (int q = 0; q < 4; q++) acc[mi][nj][q] = 0.f;

    // stage: A 128 rows x 4 chunks (512 = 1/thread); B 256 rows x 4 chunks (1024 = 2/thread)
    auto stage2 = [&](int buf, int k0) {
        {
            int r = tid >> 2;
            int c = (tid & 3) * 8;
            const __half* g = g_agg1h + (size_t)(m0 + r) * K + k0 + c;   // M=2048, always valid
            cp_async16(&As[buf][r][c], g, true);
        }
#pragma unroll
        for (int j = 0; j < 2; j++) {
            int q = tid + 512 * j;
            int r = q >> 2;
            int c = (q & 3) * 8;
            bool p = (n0 + r) < N;
            size_t grow = p ? (size_t)(n0 + r) : 0;
            const __half* g = g_w2t + grow * K + k0 + c;
            cp_async16(&Bs[buf][r][c], g, p);
        }
    };

    stage2(0, 0);
    cp_commit();
    stage2(1, 32);
    cp_commit();

    int a_row_off = wm + (lane & 7) + ((lane >> 3) & 1) * 8;
    int a_col_off = (lane >> 4) * 8;
    int b_row_off = wn + (lane & 7) + (lane >> 4) * 8;
    int b_col_off = ((lane >> 3) & 1) * 8;

    for (int i = 0; i < NI; i++) {
        cp_wait<1>();
        __syncthreads();
        const __half (*Ab)[BKP] = As[i & 1];
        const __half (*Bb)[BKP] = Bs[i & 1];
#pragma unroll
        for (int ks = 0; ks < 2; ks++) {
            int kb = ks * 16;
            uint32_t af[4][4];
            uint32_t bf[4][2];
            uint32_t abase = (uint32_t)__cvta_generic_to_shared(&Ab[a_row_off][kb + a_col_off]);
#pragma unroll
            for (int mi = 0; mi < 4; mi++) {
                asm volatile("ldmatrix.sync.aligned.m8n8.x4.shared.b16 {%0,%1,%2,%3}, [%4];"
                             : "=r"(af[mi][0]), "=r"(af[mi][1]), "=r"(af[mi][2]), "=r"(af[mi][3])
                             : "r"(abase + (uint32_t)(mi * 16 * BKP * 2)));
            }
            uint32_t bbase = (uint32_t)__cvta_generic_to_shared(&Bb[b_row_off][kb + b_col_off]);
#pragma unroll
            for (int p = 0; p < 2; p++) {
                asm volatile("ldmatrix.sync.aligned.m8n8.x4.shared.b16 {%0,%1,%2,%3}, [%4];"
                             : "=r"(bf[2 * p][0]), "=r"(bf[2 * p][1]),
                               "=r"(bf[2 * p + 1][0]), "=r"(bf[2 * p + 1][1])
                             : "r"(bbase + (uint32_t)(p * 16 * BKP * 2)));
            }
#pragma unroll
            for (int mi = 0; mi < 4; mi++)
#pragma unroll
                for (int nj = 0; nj < 4; nj++)
                    mma_f16(acc[mi][nj], af[mi], bf[nj]);
        }
        __syncthreads();
        if (i + 2 < NI) stage2(i & 1, (i + 2) * 32);
        cp_commit();
    }

    int er = lane >> 2;
    int ec = (lane & 3) * 2;
#pragma unroll
    for (int mi = 0; mi < 4; mi++) {
#pragma unroll
        for (int half_ = 0; half_ < 2; half_++) {
            int gm = m0 + wm + mi * 16 + er + half_ * 8;
#pragma unroll
            for (int nj = 0; nj < 4; nj++) {
                int gn = n0 + wn + nj * 8 + ec;
                if (gn >= N) continue;   // N even => gn+1 < N too
                float v0 = acc[mi][nj][half_ * 2 + 0] + bias[gn];
                float v1 = acc[mi][nj][half_ * 2 + 1] + bias[gn + 1];
                v0 = 1.f / (1.f + __expf(-v0));
                v1 = 1.f / (1.f + __expf(-v1));
                *(float2*)&Cout[(size_t)gm * N + gn] = make_float2(v0, v1);
            }
        }
    }
}

// ---------------- launch ----------------
extern "C" void kernel_launch(void* const* d_in, const int* in_sizes, int n_in,
                              void* d_out, int out_size) {
    const float* x  = (const float*)d_in[0];
    const float* W1 = (const float*)d_in[1];
    const float* b1 = (const float*)d_in[2];
    const float* W2 = (const float*)d_in[3];
    const float* b2 = (const float*)d_in[4];
    const int* e0_src = (const int*)d_in[5];
    const int* e0_dst = (const int*)d_in[6];
    const int* e1_src = (const int*)d_in[7];
    const int* e1_dst = (const int*)d_in[8];
    float* out = (float*)d_out;

    int E0 = in_sizes[5];
    int E1 = in_sizes[7];

    // one-time side stream + events + smem attribute (first, uncaptured call)
    static cudaStream_t s1 = nullptr;
    static cudaEvent_t ev_fork = nullptr, ev_join = nullptr;
    if (s1 == nullptr) {
        cudaStreamCreateWithFlags(&s1, cudaStreamNonBlocking);
        cudaEventCreateWithFlags(&ev_fork, cudaEventDisableTiming);
        cudaEventCreateWithFlags(&ev_join, cudaEventDisableTiming);
        cudaFuncSetAttribute(mma_gemm2_kernel,
                             cudaFuncAttributeMaxDynamicSharedMemorySize, G2_SMEM);
    }

    // fork: side stream runs the graph-setup chain
    cudaEventRecord(ev_fork, 0);
    cudaStreamWaitEvent(s1, ev_fork, 0);

    zero_counts_kernel<<<256, 256, 0, s1>>>();
    degree_kernel<<<1024, 256, 0, s1>>>(e0_src, e0_dst, e1_src, e1_dst, E0, E1);
    rsqrt_scans_kernel<<<RS_BLOCKS + 2, 1024, 0, s1>>>();
    scatters_kernel<<<1280, 256, 0, s1>>>(e0_src, e0_dst, e1_src, e1_dst, E0, E1);
    cudaEventRecord(ev_join, s1);

    // legacy stream: convert + transposes in parallel
    conv_kernel<<<CB_TOTAL, 256>>>(x, W1, W2);

    // join
    cudaStreamWaitEvent(0, ev_join, 0);

    aggregate0_kernel<<<NN1, 64>>>();

    aggregate1p_kernel<<<NN2, 64>>>();

    {
        dim3 grid((DHID + 127) / 128, NN2 / 128);   // 8 x 16
        mma_gemm1_kernel<<<grid, 256>>>(b1);
    }

    {
        dim3 grid((NCLS + 255) / 256, NN2 / 128);   // 20 x 16
        mma_gemm2_kernel<<<grid, 512, G2_SMEM>>>(b2, out);
    }
}

// round 17
// speedup vs baseline: 1.0789x; 1.0740x over previous
#include <cuda_runtime.h>
#include <cuda_fp16.h>
#include <cstdint>

// Problem constants (fixed shapes from reference setup_inputs)
#define NN0 50000
#define NN1 10000
#define NN2 2048
#define DIN 256
#define DHID 1000
#define NCLS 5000
#define EE0 500000
#define EE1 100000
#define KP2 1024   // K of GEMM2 padded to 1024 (zero fill)

// ---------------- device scratch (static, allocation-free) ----------------
__device__ int    g_cnt_out0[NN0];
__device__ int    g_cnt_in0[NN1];
__device__ int    g_cnt_out1[NN1];
__device__ int    g_cnt_in1[NN2];
__device__ float  g_rs_out0[NN0];
__device__ float  g_rs_in0[NN1];
__device__ float  g_rs_out1[NN1];
__device__ float  g_rs_in1[NN2];
__device__ int    g_off0[NN1 + 1];
__device__ int    g_cur0[NN1];
__device__ int    g_off1[NN2 + 1];
__device__ int    g_cur1[NN2];
__device__ int    g_srcs0[EE0];
__device__ int    g_srcs1[EE1];
__device__ __half g_xh[(size_t)NN0 * DIN];       // 25.6 MB  x in fp16
__device__ __half g_agg0h[(size_t)NN1 * DIN];    // 5.1 MB   layer0 aggregate (fp16)
__device__ __half g_w1t[(size_t)DHID * DIN];     // 0.5 MB   W1^T [n][k] fp16
__device__ __half g_g1[(size_t)NN2 * DIN];       // 1 MB     G = rs_in1 * sum rs_out1*agg0 (fp16)
__device__ float  g_csum[NN2];                   // rs_in1 * sum rs_out1 (bias coefficient)
__device__ __half g_agg1h[(size_t)NN2 * KP2];    // 4.2 MB   layer1 pre-GEMM2 A (fp16, k-padded;
                                                 //          pad cols [1000,1024) stay 0 forever)
__device__ __half g_w2t[(size_t)NCLS * KP2];     // 10.2 MB  W2^T [n][k] fp16 (k-padded)

// ---------------- helpers ----------------
__device__ __forceinline__ void cp_async16(void* smem_dst, const void* gsrc, bool pred) {
    uint32_t saddr = (uint32_t)__cvta_generic_to_shared(smem_dst);
    int sz = pred ? 16 : 0;
    asm volatile("cp.async.cg.shared.global [%0], [%1], 16, %2;\n"
                 :: "r"(saddr), "l"(gsrc), "r"(sz));
}
__device__ __forceinline__ void cp_commit() { asm volatile("cp.async.commit_group;\n"); }
template <int NMAX>
__device__ __forceinline__ void cp_wait() { asm volatile("cp.async.wait_group %0;\n" :: "n"(NMAX)); }

__device__ __forceinline__ void mma_f16(float* d, const uint32_t* a, const uint32_t* b) {
    asm volatile(
        "mma.sync.aligned.m16n8k16.row.col.f32.f16.f16.f32 "
        "{%0,%1,%2,%3}, {%4,%5,%6,%7}, {%8,%9}, {%0,%1,%2,%3};\n"
        : "+f"(d[0]), "+f"(d[1]), "+f"(d[2]), "+f"(d[3])
        : "r"(a[0]), "r"(a[1]), "r"(a[2]), "r"(a[3]), "r"(b[0]), "r"(b[1]));
}

// sigmoid pair via tanh.approx.f16x2: 1 MUFU op per 2 elements
__device__ __forceinline__ float2 sigmoid2_fast(float v0, float v1) {
    __half2 hz = __floats2half2_rn(v0 * 0.5f, v1 * 0.5f);
    uint32_t hzb = *(uint32_t*)&hz, tb;
    asm("tanh.approx.f16x2 %0, %1;" : "=r"(tb) : "r"(hzb));
    __half2 th = *(__half2*)&tb;
    float2 tf = __half22float2(th);
    return make_float2(fmaf(0.5f, tf.x, 0.5f), fmaf(0.5f, tf.y, 0.5f));
}

// ---------------- conv kernel: convert x->fp16 | transpose W1,W2 (legacy stream) ------------
#define CB_CONV 800
#define CB_W1 256           // 32 n-tiles x 8 k-tiles
#define CB_W2 5024          // 157 n-tiles x 32 k-tiles
#define CB_TOTAL (CB_CONV + CB_W1 + CB_W2)

__device__ __forceinline__ void transpose_tile(const float* __restrict__ W, __half* __restrict__ Wt,
                                               int K, int N, int KPad, int nb, int kb, int tid) {
    __shared__ float tile[32][33];
    int tx = tid & 31, ty = tid >> 5;  // (32,8)
#pragma unroll
    for (int i = 0; i < 32; i += 8) {
        int gk = kb + ty + i, gn = nb + tx;
        float v = 0.f;
        if (gk < K && gn < N) v = W[(size_t)gk * N + gn];
        tile[ty + i][tx] = v;
    }
    __syncthreads();
#pragma unroll
    for (int i = 0; i < 32; i += 8) {
        int gn = nb + ty + i, gk = kb + tx;
        if (gn < N && gk < KPad)
            Wt[(size_t)gn * KPad + gk] = __float2half(tile[tx][ty + i]);
    }
}

__global__ void __launch_bounds__(256) conv_kernel(const float* __restrict__ x,
                                                   const float* __restrict__ W1,
                                                   const float* __restrict__ W2) {
    int bid = blockIdx.x;
    int tid = threadIdx.x;
    if (bid < CB_CONV) {
        int i = bid * 256 + tid;
        int n4 = NN0 * DIN / 4;
        int stride = CB_CONV * 256;
        for (; i < n4; i += stride) {
            float4 v = ((const float4*)x)[i];
            __half2 h0 = __floats2half2_rn(v.x, v.y);
            __half2 h1 = __floats2half2_rn(v.z, v.w);
            uint2 u;
            u.x = *(uint32_t*)&h0;
            u.y = *(uint32_t*)&h1;
            ((uint2*)g_xh)[i] = u;
        }
    } else if (bid < CB_CONV + CB_W1) {
        int b = bid - CB_CONV;
        int nb = (b & 31) * 32;
        int kb = (b >> 5) * 32;
        transpose_tile(W1, g_w1t, DIN, DHID, DIN, nb, kb, tid);
    } else {
        int b = bid - CB_CONV - CB_W1;
        int nb = (b % 157) * 32;
        int kb = (b / 157) * 32;
        transpose_tile(W2, g_w2t, DHID, NCLS, KP2, nb, kb, tid);
    }
}

// ---------------- setup chain (side stream) ----------------
__global__ void zero_counts_kernel() {
    int i = blockIdx.x * blockDim.x + threadIdx.x;
    int stride = gridDim.x * blockDim.x;
    for (int j = i; j < NN0; j += stride) g_cnt_out0[j] = 0;
    for (int j = i; j < NN1; j += stride) { g_cnt_in0[j] = 0; g_cnt_out1[j] = 0; }
    for (int j = i; j < NN2; j += stride) g_cnt_in1[j] = 0;
}

__global__ void degree_kernel(const int* __restrict__ s0, const int* __restrict__ d0,
                              const int* __restrict__ s1, const int* __restrict__ d1,
                              int E0, int E1) {
    int i = blockIdx.x * blockDim.x + threadIdx.x;
    int stride = gridDim.x * blockDim.x;
    for (int j = i; j < E0; j += stride) {
        atomicAdd(&g_cnt_out0[s0[j]], 1);
        atomicAdd(&g_cnt_in0[d0[j]], 1);
        if (j < E1) {
            atomicAdd(&g_cnt_out1[s1[j]], 1);
            atomicAdd(&g_cnt_in1[d1[j]], 1);
        }
    }
}

__device__ __forceinline__ void scan_impl(const int* cnt, int* off, int* cur, int NB) {
    __shared__ int wsum[32];
    int t = threadIdx.x, lane = t & 31, w = t >> 5;
    int IPT = (NB + 1023) / 1024;
    int base = t * IPT;
    int loc[10];
    int s = 0;
    for (int i = 0; i < IPT; i++) {
        int b = base + i;
        int v = (b < NB) ? cnt[b] : 0;
        loc[i] = s;
        s += v;
    }
    int x = s;
    for (int d = 1; d < 32; d <<= 1) {
        int y = __shfl_up_sync(0xffffffffu, x, d);
        if (lane >= d) x += y;
    }
    if (lane == 31) wsum[w] = x;
    __syncthreads();
    if (w == 0) {
        int y = wsum[lane];
        int z = y;
        for (int d = 1; d < 32; d <<= 1) {
            int u = __shfl_up_sync(0xffffffffu, z, d);
            if (lane >= d) z += u;
        }
        wsum[lane] = z - y;
    }
    __syncthreads();
    int excl = (x - s) + wsum[w];
    for (int i = 0; i < IPT; i++) {
        int b = base + i;
        if (b < NB) {
            int o = excl + loc[i];
            off[b] = o;
            cur[b] = o;
        }
    }
    if (t == 1023) off[NB] = excl + s;
}

#define RS_BLOCKS 64
__global__ void __launch_bounds__(1024) rsqrt_scans_kernel() {
    int bid = blockIdx.x;
    if (bid == 0) { scan_impl(g_cnt_in0, g_off0, g_cur0, NN1); return; }
    if (bid == 1) { scan_impl(g_cnt_in1, g_off1, g_cur1, NN2); return; }
    int i = (bid - 2) * 1024 + threadIdx.x;
    int stride = RS_BLOCKS * 1024;
    for (int j = i; j < NN0; j += stride)
        g_rs_out0[j] = rsqrtf((float)max(g_cnt_out0[j], 1));
    for (int j = i; j < NN1; j += stride) {
        g_rs_in0[j]  = rsqrtf((float)max(g_cnt_in0[j], 1));
        g_rs_out1[j] = rsqrtf((float)max(g_cnt_out1[j], 1));
    }
    for (int j = i; j < NN2; j += stride)
        g_rs_in1[j]  = rsqrtf((float)max(g_cnt_in1[j], 1));
}

__global__ void scatters_kernel(const int* __restrict__ s0, const int* __restrict__ d0,
                                const int* __restrict__ s1, const int* __restrict__ d1,
                                int E0, int E1) {
    if (blockIdx.x < 1024) {
        int i = blockIdx.x * blockDim.x + threadIdx.x;
        int stride = 1024 * blockDim.x;
        for (int j = i; j < E0; j += stride) {
            int d = d0[j];
            int p = atomicAdd(&g_cur0[d], 1);
            g_srcs0[p] = s0[j];
        }
    } else {
        int i = (blockIdx.x - 1024) * blockDim.x + threadIdx.x;
        int stride = 256 * blockDim.x;
        for (int j = i; j < E1; j += stride) {
            int d = d1[j];
            int p = atomicAdd(&g_cur1[d], 1);
            g_srcs1[p] = s1[j];
        }
    }
}

// ---------------- layer-0 aggregation (fp16 gather, fp32 accum, fp16 out) ----------------
__global__ void __launch_bounds__(64) aggregate0_kernel() {
    int row = blockIdx.x;
    int t = threadIdx.x;
    int beg = g_off0[row], end = g_off0[row + 1];
    const uint2* x2 = (const uint2*)g_xh;
    float4 acc = make_float4(0.f, 0.f, 0.f, 0.f);
    int e = beg;
    for (; e + 1 < end; e += 2) {
        int s0 = g_srcs0[e], s1 = g_srcs0[e + 1];
        float c0 = g_rs_out0[s0], c1 = g_rs_out0[s1];
        uint2 u0 = x2[(size_t)s0 * (DIN / 4) + t];
        uint2 u1 = x2[(size_t)s1 * (DIN / 4) + t];
        float2 a0 = __half22float2(*(__half2*)&u0.x);
        float2 a1 = __half22float2(*(__half2*)&u0.y);
        float2 b0 = __half22float2(*(__half2*)&u1.x);
        float2 b1 = __half22float2(*(__half2*)&u1.y);
        acc.x = fmaf(a0.x, c0, acc.x); acc.y = fmaf(a0.y, c0, acc.y);
        acc.z = fmaf(a1.x, c0, acc.z); acc.w = fmaf(a1.y, c0, acc.w);
        acc.x = fmaf(b0.x, c1, acc.x); acc.y = fmaf(b0.y, c1, acc.y);
        acc.z = fmaf(b1.x, c1, acc.z); acc.w = fmaf(b1.y, c1, acc.w);
    }
    if (e < end) {
        int s0 = g_srcs0[e];
        float c0 = g_rs_out0[s0];
        uint2 u0 = x2[(size_t)s0 * (DIN / 4) + t];
        float2 a0 = __half22float2(*(__half2*)&u0.x);
        float2 a1 = __half22float2(*(__half2*)&u0.y);
        acc.x = fmaf(a0.x, c0, acc.x); acc.y = fmaf(a0.y, c0, acc.y);
        acc.z = fmaf(a1.x, c0, acc.z); acc.w = fmaf(a1.y, c0, acc.w);
    }
    float sd = g_rs_in0[row];
    __half2 o0 = __floats2half2_rn(acc.x * sd, acc.y * sd);
    __half2 o1 = __floats2half2_rn(acc.z * sd, acc.w * sd);
    uint2 ou;
    ou.x = *(uint32_t*)&o0;
    ou.y = *(uint32_t*)&o1;
    ((uint2*)g_agg0h)[(size_t)row * (DIN / 4) + t] = ou;
}

// ---------------- layer-1 pre-aggregation in INPUT space (256-dim) ----------
// G[d] = rs_in1[d] * sum_{e:dst=d} rs_out1[src]*agg0[src];  csum[d] = rs_in1[d]*sum rs_out1[src]
__global__ void __launch_bounds__(64) aggregate1p_kernel() {
    int row = blockIdx.x;
    int t = threadIdx.x;
    int beg = g_off1[row], end = g_off1[row + 1];
    const uint2* a2 = (const uint2*)g_agg0h;
    float4 acc = make_float4(0.f, 0.f, 0.f, 0.f);
    float cs = 0.f;
    int e = beg;
    for (; e + 1 < end; e += 2) {
        int s0 = g_srcs1[e], s1 = g_srcs1[e + 1];
        float c0 = g_rs_out1[s0], c1 = g_rs_out1[s1];
        cs += c0 + c1;
        uint2 u0 = a2[(size_t)s0 * (DIN / 4) + t];
        uint2 u1 = a2[(size_t)s1 * (DIN / 4) + t];
        float2 a0 = __half22float2(*(__half2*)&u0.x);
        float2 a1 = __half22float2(*(__half2*)&u0.y);
        float2 b0 = __half22float2(*(__half2*)&u1.x);
        float2 b1 = __half22float2(*(__half2*)&u1.y);
        acc.x = fmaf(a0.x, c0, acc.x); acc.y = fmaf(a0.y, c0, acc.y);
        acc.z = fmaf(a1.x, c0, acc.z); acc.w = fmaf(a1.y, c0, acc.w);
        acc.x = fmaf(b0.x, c1, acc.x); acc.y = fmaf(b0.y, c1, acc.y);
        acc.z = fmaf(b1.x, c1, acc.z); acc.w = fmaf(b1.y, c1, acc.w);
    }
    if (e < end) {
        int s0 = g_srcs1[e];
        float c0 = g_rs_out1[s0];
        cs += c0;
        uint2 u0 = a2[(size_t)s0 * (DIN / 4) + t];
        float2 a0 = __half22float2(*(__half2*)&u0.x);
        float2 a1 = __half22float2(*(__half2*)&u0.y);
        acc.x = fmaf(a0.x, c0, acc.x); acc.y = fmaf(a0.y, c0, acc.y);
        acc.z = fmaf(a1.x, c0, acc.z); acc.w = fmaf(a1.y, c0, acc.w);
    }
    float sd = g_rs_in1[row];
    __half2 o0 = __floats2half2_rn(acc.x * sd, acc.y * sd);
    __half2 o1 = __floats2half2_rn(acc.z * sd, acc.w * sd);
    uint2 ou;
    ou.x = *(uint32_t*)&o0;
    ou.y = *(uint32_t*)&o1;
    ((uint2*)g_g1)[(size_t)row * (DIN / 4) + t] = ou;
    if (t == 0) g_csum[row] = cs * sd;
}

// ---------------- fp16 GEMMs: 128x128 tile, 256 thr, 2-stage cp.async + ldmatrix ----------
// LAYER==1 (fused): A=g_g1 [2048,256], B=g_w1t [1000,256],
//                   epi: acc + csum[m]*b1[n] -> g_agg1h (fp16, row stride KP2)
// LAYER==2:         A=g_agg1h [2048,1024], B=g_w2t [5000,1024],
//                   epi: sigmoid(acc + b2[n]) via tanh.approx.f16x2 -> d_out (fp32)
#define BKP 40  // 32 + 8-half pad -> 80B row stride, conflict-free ldmatrix

__device__ __forceinline__ void stage_tile(__half (*S)[BKP], const __half* __restrict__ src,
                                           int rowbase, int rowlim, int k0, int kstride, int tid) {
    int r = tid >> 1;
    int c = (tid & 1) * 16;
    bool p = (rowbase + r) < rowlim;
    size_t grow = p ? (size_t)(rowbase + r) : 0;
    const __half* g = src + grow * kstride + k0 + c;
    cp_async16(&S[r][c], g, p);
    cp_async16(&S[r][c + 8], g + 8, p);
}

template <int LAYER>
__global__ void __launch_bounds__(256) mma_gemm_kernel(const float* __restrict__ bias,
                                                       float* __restrict__ Cout) {
    constexpr int M = NN2;                            // 2048 for both layers
    constexpr int N = (LAYER == 1) ? DHID : NCLS;
    constexpr int K = (LAYER == 1) ? DIN : KP2;
    constexpr int NI = K / 32;

    const __half* __restrict__ Ah = (LAYER == 1) ? g_g1 : g_agg1h;
    const __half* __restrict__ Bh = (LAYER == 1) ? g_w1t : g_w2t;

    __shared__ __align__(16) __half As[2][128][BKP];
    __shared__ __align__(16) __half Bs[2][128][BKP];

    int tid = threadIdx.x;
    int lane = tid & 31;
    int wid = tid >> 5;
    int wm = (wid >> 2) * 64;
    int wn = (wid & 3) * 32;
    int m0 = blockIdx.y * 128, n0 = blockIdx.x * 128;

    float acc[4][4][4];
#pragma unroll
    for (int mi = 0; mi < 4; mi++)
#pragma unroll
        for (int nj = 0; nj < 4; nj++)
#pragma unroll
            for (int q = 0; q < 4; q++) acc[mi][nj][q] = 0.f;

    stage_tile(As[0], Ah, m0, M, 0, K, tid);
    stage_tile(Bs[0], Bh, n0, N, 0, K, tid);
    cp_commit();
    stage_tile(As[1], Ah, m0, M, 32, K, tid);
    stage_tile(Bs[1], Bh, n0, N, 32, K, tid);
    cp_commit();

    // ldmatrix lane address components (verified against m16n8k16 fragment spec)
    int a_row_off = wm + (lane & 7) + ((lane >> 3) & 1) * 8;  // + mi*16
    int a_col_off = (lane >> 4) * 8;                           // + kb
    int b_row_off = wn + (lane & 7) + (lane >> 4) * 8;         // + p*16
    int b_col_off = ((lane >> 3) & 1) * 8;                     // + kb

    for (int i = 0; i < NI; i++) {
        cp_wait<1>();
        __syncthreads();
        const __half (*Ab)[BKP] = As[i & 1];
        const __half (*Bb)[BKP] = Bs[i & 1];
#pragma unroll
        for (int ks = 0; ks < 2; ks++) {
            int kb = ks * 16;
            uint32_t af[4][4];
            uint32_t bf[4][2];
            uint32_t abase = (uint32_t)__cvta_generic_to_shared(&Ab[a_row_off][kb + a_col_off]);
#pragma unroll
            for (int mi = 0; mi < 4; mi++) {
                asm volatile("ldmatrix.sync.aligned.m8n8.x4.shared.b16 {%0,%1,%2,%3}, [%4];"
                             : "=r"(af[mi][0]), "=r"(af[mi][1]), "=r"(af[mi][2]), "=r"(af[mi][3])
                             : "r"(abase + (uint32_t)(mi * 16 * BKP * 2)));
            }
            uint32_t bbase = (uint32_t)__cvta_generic_to_shared(&Bb[b_row_off][kb + b_col_off]);
#pragma unroll
            for (int p = 0; p < 2; p++) {
                asm volatile("ldmatrix.sync.aligned.m8n8.x4.shared.b16 {%0,%1,%2,%3}, [%4];"
                             : "=r"(bf[2 * p][0]), "=r"(bf[2 * p][1]),
                               "=r"(bf[2 * p + 1][0]), "=r"(bf[2 * p + 1][1])
                             : "r"(bbase + (uint32_t)(p * 16 * BKP * 2)));
            }
#pragma unroll
            for (int mi = 0; mi < 4; mi++)
#pragma unroll
                for (int nj = 0; nj < 4; nj++)
                    mma_f16(acc[mi][nj], af[mi], bf[nj]);
        }
        __syncthreads();
        if (i + 2 < NI) {
            stage_tile(As[i & 1], Ah, m0, M, (i + 2) * 32, K, tid);
            stage_tile(Bs[i & 1], Bh, n0, N, (i + 2) * 32, K, tid);
        }
        cp_commit();
    }

    int er = lane >> 2;
    int ec = (lane & 3) * 2;
#pragma unroll
    for (int mi = 0; mi < 4; mi++) {
#pragma unroll
        for (int half_ = 0; half_ < 2; half_++) {
            int gm = m0 + wm + mi * 16 + er + half_ * 8;
            if (gm >= M) continue;
            float cw = (LAYER == 1) ? g_csum[gm] : 1.f;
#pragma unroll
            for (int nj = 0; nj < 4; nj++) {
                int gn = n0 + wn + nj * 8 + ec;
                if (gn >= N) continue;
                if (LAYER == 1) {
                    float v0 = acc[mi][nj][half_ * 2 + 0] + cw * bias[gn];
                    float v1 = acc[mi][nj][half_ * 2 + 1] + cw * bias[gn + 1];
                    __half2 h = __floats2half2_rn(v0, v1);
                    *(uint32_t*)&g_agg1h[(size_t)gm * KP2 + gn] = *(uint32_t*)&h;
                } else {
                    float v0 = acc[mi][nj][half_ * 2 + 0] + bias[gn];
                    float v1 = acc[mi][nj][half_ * 2 + 1] + bias[gn + 1];
                    float2 sg = sigmoid2_fast(v0, v1);
                    *(float2*)&Cout[(size_t)gm * N + gn] = sg;
                }
            }
        }
    }
}

// ---------------- launch ----------------
extern "C" void kernel_launch(void* const* d_in, const int* in_sizes, int n_in,
                              void* d_out, int out_size) {
    const float* x  = (const float*)d_in[0];
    const float* W1 = (const float*)d_in[1];
    const float* b1 = (const float*)d_in[2];
    const float* W2 = (const float*)d_in[3];
    const float* b2 = (const float*)d_in[4];
    const int* e0_src = (const int*)d_in[5];
    const int* e0_dst = (const int*)d_in[6];
    const int* e1_src = (const int*)d_in[7];
    const int* e1_dst = (const int*)d_in[8];
    float* out = (float*)d_out;

    int E0 = in_sizes[5];
    int E1 = in_sizes[7];

    // one-time side stream + events (created on the uncaptured correctness call)
    static cudaStream_t s1 = nullptr;
    static cudaEvent_t ev_fork = nullptr, ev_join = nullptr;
    if (s1 == nullptr) {
        cudaStreamCreateWithFlags(&s1, cudaStreamNonBlocking);
        cudaEventCreateWithFlags(&ev_fork, cudaEventDisableTiming);
        cudaEventCreateWithFlags(&ev_join, cudaEventDisableTiming);
    }

    // fork: side stream runs the graph-setup chain
    cudaEventRecord(ev_fork, 0);
    cudaStreamWaitEvent(s1, ev_fork, 0);

    zero_counts_kernel<<<256, 256, 0, s1>>>();
    degree_kernel<<<1024, 256, 0, s1>>>(e0_src, e0_dst, e1_src, e1_dst, E0, E1);
    rsqrt_scans_kernel<<<RS_BLOCKS + 2, 1024, 0, s1>>>();
    scatters_kernel<<<1280, 256, 0, s1>>>(e0_src, e0_dst, e1_src, e1_dst, E0, E1);
    cudaEventRecord(ev_join, s1);

    // legacy stream: convert + transposes in parallel
    conv_kernel<<<CB_TOTAL, 256>>>(x, W1, W2);

    // join
    cudaStreamWaitEvent(0, ev_join, 0);

    aggregate0_kernel<<<NN1, 64>>>();

    aggregate1p_kernel<<<NN2, 64>>>();

    {
        dim3 grid((DHID + 127) / 128, NN2 / 128);   // 8 x 16
        mma_gemm_kernel<1><<<grid, 256>>>(b1, nullptr);
    }

    {
        dim3 grid((NCLS + 127) / 128, NN2 / 128);   // 40 x 16
        mma_gemm_kernel<2><<<grid, 256>>>(b2, out);
    }
}